// round 10
// baseline (speedup 1.0000x reference)
#include <cuda_runtime.h>

#define S 2048
#define B 64
#define H 8
#define KK 12
#define NPOS 11
#define TBL 4096  // 1<<KK

// Scratch (__device__ globals; no allocations allowed).
__device__ unsigned long long g_tokmask[S]; // 64 token bits per row
__device__ uint4 g_AQ4[S];                  // per s: 8 x u16 = (h<<12) + addr_q
__device__ uint4 g_AK4[S];                  // per s: 8 x u16 = addr_k
__device__ uint4 g_AP4[S];                  // per rel: 8 x u16 = addr_p
__device__ uint4 g_tbw4[H * TBL / 32 / 4];  // bit table: word i, bit j = head_table[i*32+j]
__device__ int g_best[S];                   // per row: (max_vote<<11) | (2047 - argmax_k)

// ---------------------------------------------------------------------------
// Prep: one warp per row s (ballot mask; lanes 0..7 compute per-head partial
// addresses — the three groups partition the 12 bits, so aq+ak+ap <= 4095).
// First 1024 threads also build the bit table from float4 loads.
__global__ void __launch_bounds__(256) k_prep(
        const int* __restrict__ tokens,
        const int* __restrict__ conn_heads,
        const float* __restrict__ head_table) {
    int tid = threadIdx.x;
    int lane = tid & 31;
    int gw = blockIdx.x * 8 + (tid >> 5);    // row index, 0..2047

    int t0 = tokens[gw * B + lane];
    int t1 = tokens[gw * B + 32 + lane];
    unsigned lo = __ballot_sync(0xffffffffu, t0 != 0);
    unsigned hi = __ballot_sync(0xffffffffu, t1 != 0);
    unsigned long long tm = (unsigned long long)lo | ((unsigned long long)hi << 32);
    if (lane == 0) g_tokmask[gw] = tm;

    if (lane < H) {
        int h = lane;
        int aq = 0, ak = 0, ap = 0;
#pragma unroll
        for (int j = 0; j < KK; j++) {
            int c = __ldg(&conn_heads[h * KK + j]);
            int p2 = 1 << (KK - 1 - j);
            if (c < B)          aq += (int)((tm >> c) & 1ull) * p2;
            else if (c < 2 * B) ak += (int)((tm >> (c - B)) & 1ull) * p2;
            else                ap += ((gw >> (NPOS - 1 - (c - 2 * B))) & 1) * p2;
        }
        int i = gw * 8 + h;
        ((unsigned short*)g_AQ4)[i] = (unsigned short)((h << 12) + aq);
        ((unsigned short*)g_AK4)[i] = (unsigned short)ak;
        ((unsigned short*)g_AP4)[i] = (unsigned short)ap;
    }

    int i = blockIdx.x * 256 + tid;
    if (i < H * TBL / 32) {                  // 1024 table words
        const float4* ht4 = (const float4*)head_table;
        unsigned w = 0;
#pragma unroll
        for (int r = 0; r < 8; r++) {
            float4 f = __ldg(&ht4[i * 8 + r]);
            w |= (unsigned)(f.x != 0.0f) << (r * 4);
            w |= (unsigned)(f.y != 0.0f) << (r * 4 + 1);
            w |= (unsigned)(f.z != 0.0f) << (r * 4 + 2);
            w |= (unsigned)(f.w != 0.0f) << (r * 4 + 3);
        }
        ((unsigned*)g_tbw4)[i] = w;
    }
}

// ---------------------------------------------------------------------------
// Scan: one 128-thread block per query row q; 4KB bit table staged per block.
// 512-wide chunks (4 keys per thread, independent LDS chains), ascending,
// with in-loop prefetch and one __syncthreads_or per chunk; exit when any
// vote hits the max (H) or keys are exhausted. Writes encoded best per row;
// enc = (v<<11)|(2047-k) gives max-vote with first-index tie-break.
__global__ void __launch_bounds__(128) k_scan(int* __restrict__ best_out) {
    __shared__ unsigned s_tb[H * TBL / 32];   // 1024 words = 4 KB
    __shared__ int s_red[4];

    int tid = threadIdx.x;
    int q = blockIdx.x;

    // Issue all chunk-0 loads + staging loads up front (overlap latencies).
    uint4 tb0 = g_tbw4[tid];
    uint4 tb1 = g_tbw4[tid + 128];
    uint4 aq  = g_AQ4[q];
    uint4 ak[4], ap[4];
#pragma unroll
    for (int j = 0; j < 4; j++) {
        int kc = min(j * 128 + tid, q);
        ak[j] = __ldg(&g_AK4[kc]);
        ap[j] = __ldg(&g_AP4[q - kc]);
    }
    ((uint4*)s_tb)[tid] = tb0;
    ((uint4*)s_tb)[tid + 128] = tb1;
    __syncthreads();

    int best = -1;
    for (int base = 0;;) {
        int hit = 0;
#pragma unroll
        for (int j = 0; j < 4; j++) {
            int k = base + j * 128 + tid;
            bool valid = (k <= q);
            // packed u16 adds: (h<<12)+(aq+ak+ap) <= 32767 per lane, no carry
            unsigned wx = ak[j].x + ap[j].x + aq.x;
            unsigned wy = ak[j].y + ap[j].y + aq.y;
            unsigned wz = ak[j].z + ap[j].z + aq.z;
            unsigned ww = ak[j].w + ap[j].w + aq.w;
            int v  = (s_tb[(wx & 0xFFFFu) >> 5] >> (wx & 31)) & 1;
            v += (s_tb[wx >> 21] >> ((wx >> 16) & 31)) & 1;
            v += (s_tb[(wy & 0xFFFFu) >> 5] >> (wy & 31)) & 1;
            v += (s_tb[wy >> 21] >> ((wy >> 16) & 31)) & 1;
            v += (s_tb[(wz & 0xFFFFu) >> 5] >> (wz & 31)) & 1;
            v += (s_tb[wz >> 21] >> ((wz >> 16) & 31)) & 1;
            v += (s_tb[(ww & 0xFFFFu) >> 5] >> (ww & 31)) & 1;
            v += (s_tb[ww >> 21] >> ((ww >> 16) & 31)) & 1;
            if (valid) {
                best = max(best, (v << 11) | (2047 - k));
                hit |= (int)(v == H);
            }
        }
        int nbase = base + 512;
        bool more = (nbase <= q);             // block-uniform
        if (more) {
#pragma unroll
            for (int j = 0; j < 4; j++) {
                int kc = min(nbase + j * 128 + tid, q);
                ak[j] = __ldg(&g_AK4[kc]);
                ap[j] = __ldg(&g_AP4[q - kc]);
            }
        }
        // Ascending scan: first chunk containing the global-max vote (H)
        // holds the argmax; one fused barrier+OR per chunk.
        if (__syncthreads_or(hit) || !more) break;
        base = nbase;
    }

    // Block max-reduce of encoded best (4 warps).
#pragma unroll
    for (int off = 16; off; off >>= 1)
        best = max(best, __shfl_xor_sync(0xffffffffu, best, off));
    if ((tid & 31) == 0) s_red[tid >> 5] = best;
    __syncthreads();
    if (tid == 0) {
        int m = max(max(s_red[0], s_red[1]), max(s_red[2], s_red[3]));
        best_out[q] = m;
    }
}

// ---------------------------------------------------------------------------
// Out: one thread per (q, b). Massive parallelism hides the dependent
// mask -> table_v load chain that used to serialize each scan block's tail.
__global__ void __launch_bounds__(256) k_out(
        const int* __restrict__ conn_v,
        const float* __restrict__ table_v,
        const int* __restrict__ best_in,
        float* __restrict__ out) {
    int idx = blockIdx.x * 256 + threadIdx.x;   // 0 .. S*B-1
    int q = idx >> 6, b = idx & 63;
    int m = best_in[q];
    float o = 0.0f;
    if ((m >> 11) > 0) {
        int bk = 2047 - (m & 2047);
        unsigned long long msk = g_tokmask[bk];
        int addr = 0;
#pragma unroll
        for (int j = 0; j < KK; j++) {
            int c = __ldg(&conn_v[b * KK + j]);
            addr += (int)((msk >> c) & 1ull) << (KK - 1 - j);
        }
        o = __ldg(&table_v[b * TBL + addr]);
    }
    out[idx] = o;
}

// ---------------------------------------------------------------------------
extern "C" void kernel_launch(void* const* d_in, const int* in_sizes, int n_in,
                              void* d_out, int out_size) {
    const int*   tokens     = (const int*)d_in[0];
    const int*   conn_heads = (const int*)d_in[1];
    const float* head_table = (const float*)d_in[2];
    const int*   conn_v     = (const int*)d_in[3];
    const float* table_v    = (const float*)d_in[4];
    float* out = (float*)d_out;

    int* bestp;
    cudaGetSymbolAddress((void**)&bestp, g_best);

    k_prep<<<S / 8, 256>>>(tokens, conn_heads, head_table);
    k_scan<<<S, 128>>>(bestp);
    k_out<<<(S * B) / 256, 256>>>(conn_v, table_v, bestp, out);
}

// round 11
// speedup vs baseline: 1.0204x; 1.0204x over previous
#include <cuda_runtime.h>

#define S 2048
#define B 64
#define H 8
#define KK 12
#define NPOS 11
#define TBL 4096   // 1<<KK
#define NBLK 592   // 4 blocks/SM x 148 SMs = one guaranteed wave at 32KB smem

// Scratch (__device__ globals; no allocations allowed).
__device__ unsigned long long g_tokmask[S]; // 64 token bits per row
__device__ uint4 g_AQ4[S];                  // per s: 8 x u16 = (h<<12) + addr_q
__device__ uint4 g_AK4[S];                  // per s: 8 x u16 = addr_k
__device__ uint4 g_AP4[S];                  // per rel: 8 x u16 = addr_p
__device__ uint4 g_tbB4[H * TBL / 16];      // byte table: head_table[h][addr] as u8
__device__ int g_best[S];                   // per row: (max_vote<<11) | (2047 - argmax_k)

// ---------------------------------------------------------------------------
// Prep: one warp per row s (ballot mask; lanes 0..7 compute per-head partial
// addresses — the three groups partition the 12 bits, so aq+ak+ap <= 4095).
// First 2048 threads also build the 32KB byte table from float4 loads.
__global__ void __launch_bounds__(256) k_prep(
        const int* __restrict__ tokens,
        const int* __restrict__ conn_heads,
        const float* __restrict__ head_table) {
    int tid = threadIdx.x;
    int lane = tid & 31;
    int gw = blockIdx.x * 8 + (tid >> 5);    // row index, 0..2047

    int t0 = tokens[gw * B + lane];
    int t1 = tokens[gw * B + 32 + lane];
    unsigned lo = __ballot_sync(0xffffffffu, t0 != 0);
    unsigned hi = __ballot_sync(0xffffffffu, t1 != 0);
    unsigned long long tm = (unsigned long long)lo | ((unsigned long long)hi << 32);
    if (lane == 0) g_tokmask[gw] = tm;

    if (lane < H) {
        int h = lane;
        int aq = 0, ak = 0, ap = 0;
#pragma unroll
        for (int j = 0; j < KK; j++) {
            int c = __ldg(&conn_heads[h * KK + j]);
            int p2 = 1 << (KK - 1 - j);
            if (c < B)          aq += (int)((tm >> c) & 1ull) * p2;
            else if (c < 2 * B) ak += (int)((tm >> (c - B)) & 1ull) * p2;
            else                ap += ((gw >> (NPOS - 1 - (c - 2 * B))) & 1) * p2;
        }
        int i = gw * 8 + h;
        ((unsigned short*)g_AQ4)[i] = (unsigned short)((h << 12) + aq);
        ((unsigned short*)g_AK4)[i] = (unsigned short)ak;
        ((unsigned short*)g_AP4)[i] = (unsigned short)ap;
    }

    int i = blockIdx.x * 256 + tid;
    if (i < H * TBL / 16) {                  // 2048 uint4 of bytes
        const float4* ht4 = (const float4*)head_table;
        unsigned w[4];
#pragma unroll
        for (int r = 0; r < 4; r++) {
            float4 f = __ldg(&ht4[i * 4 + r]);
            w[r] = (unsigned)(f.x != 0.0f)
                 | ((unsigned)(f.y != 0.0f) << 8)
                 | ((unsigned)(f.z != 0.0f) << 16)
                 | ((unsigned)(f.w != 0.0f) << 24);
        }
        g_tbB4[i] = make_uint4(w[0], w[1], w[2], w[3]);
    }
}

// ---------------------------------------------------------------------------
// Scan: 592 persistent-ish blocks; each stages the 32KB byte table ONCE,
// then grid-strides over query rows. Per row: ascending 256-wide chunk scan
// with prefetch and one __syncthreads_or per chunk; exit on any vote == H
// (the global max) or key exhaustion. enc = (v<<11)|(2047-k) gives max-vote
// with first-index tie-break; writes one encoded int per row.
__global__ void __launch_bounds__(256) k_scan(int* __restrict__ best_out) {
    __shared__ unsigned char s_tb[H * TBL];   // 32 KB byte table
    __shared__ int s_red[8];

    int tid = threadIdx.x;
#pragma unroll
    for (int i = 0; i < 8; i++)
        ((uint4*)s_tb)[tid + i * 256] = g_tbB4[tid + i * 256];
    __syncthreads();

    for (int q = blockIdx.x; q < S; q += NBLK) {
        uint4 aq = g_AQ4[q];
        int kc = min(tid, q);
        uint4 ak = __ldg(&g_AK4[kc]);
        uint4 ap = __ldg(&g_AP4[q - kc]);

        int best = -1;
        for (int base = 0; base <= q; base += 256) {
            int k = base + tid;
            bool valid = (k <= q);
            uint4 cak = ak, cap = ap;
            if (base + 256 <= q) {            // block-uniform prefetch
                int kn = min(base + 256 + tid, q);
                ak = __ldg(&g_AK4[kn]);
                ap = __ldg(&g_AP4[q - kn]);
            }
            // packed u16 adds: (h<<12)+(aq+ak+ap) <= 32767 per lane, no
            // carry — each u16 lane IS the byte index into s_tb.
            unsigned wx = cak.x + cap.x + aq.x;
            unsigned wy = cak.y + cap.y + aq.y;
            unsigned wz = cak.z + cap.z + aq.z;
            unsigned ww = cak.w + cap.w + aq.w;
            int v = s_tb[wx & 0xFFFFu] + s_tb[wx >> 16]
                  + s_tb[wy & 0xFFFFu] + s_tb[wy >> 16]
                  + s_tb[wz & 0xFFFFu] + s_tb[wz >> 16]
                  + s_tb[ww & 0xFFFFu] + s_tb[ww >> 16];
            if (valid) best = max(best, (v << 11) | (2047 - k));
            // Ascending scan: first chunk containing vote==H holds the argmax.
            if (__syncthreads_or((int)(valid && v == H))) break;
        }

        // Block max-reduce of encoded best (8 warps).
#pragma unroll
        for (int off = 16; off; off >>= 1)
            best = max(best, __shfl_xor_sync(0xffffffffu, best, off));
        if ((tid & 31) == 0) s_red[tid >> 5] = best;
        __syncthreads();
        if (tid == 0) {
            int m = s_red[0];
#pragma unroll
            for (int i = 1; i < 8; i++) m = max(m, s_red[i]);
            best_out[q] = m;
        }
        __syncthreads();   // protect s_red before next row reuses it
    }
}

// ---------------------------------------------------------------------------
// Out: one thread per (q, b). Massive parallelism hides the dependent
// mask -> table_v load chain.
__global__ void __launch_bounds__(256) k_out(
        const int* __restrict__ conn_v,
        const float* __restrict__ table_v,
        const int* __restrict__ best_in,
        float* __restrict__ out) {
    int idx = blockIdx.x * 256 + threadIdx.x;   // 0 .. S*B-1
    int q = idx >> 6, b = idx & 63;
    int m = best_in[q];
    float o = 0.0f;
    if ((m >> 11) > 0) {
        int bk = 2047 - (m & 2047);
        unsigned long long msk = g_tokmask[bk];
        int addr = 0;
#pragma unroll
        for (int j = 0; j < KK; j++) {
            int c = __ldg(&conn_v[b * KK + j]);
            addr += (int)((msk >> c) & 1ull) << (KK - 1 - j);
        }
        o = __ldg(&table_v[b * TBL + addr]);
    }
    out[idx] = o;
}

// ---------------------------------------------------------------------------
extern "C" void kernel_launch(void* const* d_in, const int* in_sizes, int n_in,
                              void* d_out, int out_size) {
    const int*   tokens     = (const int*)d_in[0];
    const int*   conn_heads = (const int*)d_in[1];
    const float* head_table = (const float*)d_in[2];
    const int*   conn_v     = (const int*)d_in[3];
    const float* table_v    = (const float*)d_in[4];
    float* out = (float*)d_out;

    int* bestp;
    cudaGetSymbolAddress((void**)&bestp, g_best);

    k_prep<<<S / 8, 256>>>(tokens, conn_heads, head_table);
    k_scan<<<NBLK, 256>>>(bestp);
    k_out<<<(S * B) / 256, 256>>>(conn_v, table_v, bestp, out);
}

// round 13
// speedup vs baseline: 1.2959x; 1.2700x over previous
#include <cuda_runtime.h>

#define S 2048
#define B 64
#define H 8
#define KK 12
#define NPOS 11
#define TBL 4096   // 1<<KK

// Scratch (__device__ globals; no allocations allowed).
__device__ unsigned long long g_tokmask[S]; // 64 token bits per row
__device__ uint4 g_AQ4[S];                  // per s: 8 x u16 = (h<<12) + addr_q
__device__ uint4 g_AK4[S];                  // per s: 8 x u16 = addr_k
__device__ uint4 g_AP4[S];                  // per rel: 8 x u16 = addr_p
__device__ uint4 g_tbw4[H * TBL / 32 / 4];  // bit table: word i, bit j = head_table[i*32+j]

// ---------------------------------------------------------------------------
// Prep: 512 blocks x 128 threads. One warp per row s (ballot mask; lanes 0..7
// compute per-head partial addresses — the three groups partition the 12
// bits, so aq+ak+ap <= 4095). Threads 0..1 of each block each build one bit-
// table word from 8 independent float4 loads.
__global__ void __launch_bounds__(128) k_prep(
        const int* __restrict__ tokens,
        const int* __restrict__ conn_heads,
        const float* __restrict__ head_table) {
    int tid = threadIdx.x;
    int lane = tid & 31;
    int gw = blockIdx.x * 4 + (tid >> 5);    // row index, 0..2047

    int t0 = tokens[gw * B + lane];
    int t1 = tokens[gw * B + 32 + lane];
    unsigned lo = __ballot_sync(0xffffffffu, t0 != 0);
    unsigned hi = __ballot_sync(0xffffffffu, t1 != 0);
    unsigned long long tm = (unsigned long long)lo | ((unsigned long long)hi << 32);
    if (lane == 0) g_tokmask[gw] = tm;

    if (lane < H) {
        int h = lane;
        int aq = 0, ak = 0, ap = 0;
#pragma unroll
        for (int j = 0; j < KK; j++) {
            int c = __ldg(&conn_heads[h * KK + j]);
            int p2 = 1 << (KK - 1 - j);
            if (c < B)          aq += (int)((tm >> c) & 1ull) * p2;
            else if (c < 2 * B) ak += (int)((tm >> (c - B)) & 1ull) * p2;
            else                ap += ((gw >> (NPOS - 1 - (c - 2 * B))) & 1) * p2;
        }
        int i = gw * 8 + h;
        ((unsigned short*)g_AQ4)[i] = (unsigned short)((h << 12) + aq);
        ((unsigned short*)g_AK4)[i] = (unsigned short)ak;
        ((unsigned short*)g_AP4)[i] = (unsigned short)ap;
    }

    if (tid < 2) {                            // 2 table words per block
        int wi = blockIdx.x * 2 + tid;        // 0..1023
        const float4* ht4 = (const float4*)head_table;
        unsigned w = 0;
#pragma unroll
        for (int r = 0; r < 8; r++) {
            float4 f = __ldg(&ht4[wi * 8 + r]);
            w |= (unsigned)(f.x != 0.0f) << (r * 4);
            w |= (unsigned)(f.y != 0.0f) << (r * 4 + 1);
            w |= (unsigned)(f.z != 0.0f) << (r * 4 + 2);
            w |= (unsigned)(f.w != 0.0f) << (r * 4 + 3);
        }
        ((unsigned*)g_tbw4)[wi] = w;
    }
}

// ---------------------------------------------------------------------------
// Main: each block handles TWO rows SEQUENTIALLY — q = bid and q = 2047-bid
// (short+long pairing balances total work; 4KB bit table staged once).
// Per row: ascending 256-wide chunk scan; kc=min(k,q) clamp makes all lanes
// uniform (out-of-range lanes duplicate k=q — identical enc and hit bit, so
// the max/exit are unaffected). One __syncthreads_or per chunk; exit when
// any vote hits the max (H). enc=(v<<11)|(2047-k) -> max vote, first index.
__global__ void __launch_bounds__(256) k_main(
        const int* __restrict__ conn_v,
        const float* __restrict__ table_v,
        float* __restrict__ out) {
    __shared__ unsigned s_tb[H * TBL / 32];   // 1024 words = 4 KB
    __shared__ int s_red[8];
    __shared__ int s_best;

    int tid = threadIdx.x;
    ((uint4*)s_tb)[tid] = g_tbw4[tid];        // 256 uint4 = whole table
    __syncthreads();

#pragma unroll
    for (int r = 0; r < 2; r++) {
        int q = r ? (S - 1 - (int)blockIdx.x) : (int)blockIdx.x;
        uint4 aq = g_AQ4[q];

        int best = -1;
        for (int base = 0; base <= q; base += 256) {
            int kc = min(base + tid, q);
            uint4 ak = __ldg(&g_AK4[kc]);
            uint4 ap = __ldg(&g_AP4[q - kc]);
            // packed u16 adds: (h<<12)+(aq+ak+ap) <= 32767 per lane, no carry
            unsigned wx = ak.x + ap.x + aq.x;
            unsigned wy = ak.y + ap.y + aq.y;
            unsigned wz = ak.z + ap.z + aq.z;
            unsigned ww = ak.w + ap.w + aq.w;
            // bit lookup: word = addr16>>5 (h<<12 -> region h<<7), bit = addr16&31
            int v  = (s_tb[(wx & 0xFFFFu) >> 5] >> (wx & 31)) & 1;
            v += (s_tb[wx >> 21] >> ((wx >> 16) & 31)) & 1;
            v += (s_tb[(wy & 0xFFFFu) >> 5] >> (wy & 31)) & 1;
            v += (s_tb[wy >> 21] >> ((wy >> 16) & 31)) & 1;
            v += (s_tb[(wz & 0xFFFFu) >> 5] >> (wz & 31)) & 1;
            v += (s_tb[wz >> 21] >> ((wz >> 16) & 31)) & 1;
            v += (s_tb[(ww & 0xFFFFu) >> 5] >> (ww & 31)) & 1;
            v += (s_tb[ww >> 21] >> ((ww >> 16) & 31)) & 1;
            best = max(best, (v << 11) | (2047 - kc));
            // Ascending scan: first chunk containing vote==H holds the argmax.
            if (__syncthreads_or((int)(v == H))) break;
        }

        // Block max-reduce of encoded best (8 warps).
#pragma unroll
        for (int off = 16; off; off >>= 1)
            best = max(best, __shfl_xor_sync(0xffffffffu, best, off));
        if ((tid & 31) == 0) s_red[tid >> 5] = best;
        __syncthreads();
        if (tid == 0) {
            int m = s_red[0];
#pragma unroll
            for (int i = 1; i < 8; i++) m = max(m, s_red[i]);
            s_best = m;
        }
        __syncthreads();

        if (tid < B) {
            int m = s_best;
            int bv = m >> 11;
            int bk = 2047 - (m & 2047);
            float o = 0.0f;
            if (bv > 0) {
                unsigned long long msk = g_tokmask[bk];
                int addr = 0;
#pragma unroll
                for (int j = 0; j < KK; j++) {
                    int c = __ldg(&conn_v[tid * KK + j]);
                    addr += (int)((msk >> c) & 1ull) << (KK - 1 - j);
                }
                o = __ldg(&table_v[tid * TBL + addr]);
            }
            out[q * B + tid] = o;
        }
    }
}

// ---------------------------------------------------------------------------
extern "C" void kernel_launch(void* const* d_in, const int* in_sizes, int n_in,
                              void* d_out, int out_size) {
    const int*   tokens     = (const int*)d_in[0];
    const int*   conn_heads = (const int*)d_in[1];
    const float* head_table = (const float*)d_in[2];
    const int*   conn_v     = (const int*)d_in[3];
    const float* table_v    = (const float*)d_in[4];
    float* out = (float*)d_out;

    k_prep<<<S / 4, 128>>>(tokens, conn_heads, head_table);
    k_main<<<S / 2, 256>>>(conn_v, table_v, out);
}